// round 9
// baseline (speedup 1.0000x reference)
#include <cuda_runtime.h>
#include <cuda_fp16.h>

#define NN   50000
#define EE   800000
#define HID  64
#define IND  128
#define OUTD 40
#define NBLK ((NN + 255) / 256)   // 196 scan/zero blocks
#define GB   ((NN + 63) / 64)     // 782 mma-gemm blocks (64 rows each)
#define HB   ((EE + 255) / 256)   // 3125 edge blocks
#define XV4  (NN * IND / 4)       // 1,600,000 float4s in x
#define PREPEXT (IND*64 + HID*64 + HID*64 + 192*64)   // 28672 weight elems
#define PREPB ((XV4 + PREPEXT + 255) / 256)

// ---------------- device scratch (no allocations allowed) ----------------
__device__ __half g_xh[NN * IND];
__device__ __half g_hlin[NN * HID];
__device__ __half g_h0[NN * HID];
__device__ __half g_h1[NN * HID];
__device__ __half g_h2[NN * HID];
__device__ __half g_w1[IND * 64];
__device__ __half g_w2[HID * 64];
__device__ __half g_w3[HID * 64];
__device__ __half g_wl[192 * 64];
__device__ int   g_rowptr[NN + 1];
__device__ int   g_cnt[NN];
__device__ int   g_agg[NBLK];           // scan block aggregates
__device__ int   g_flag[NBLK];          // scan publish flags
__device__ int4  g_edge4[EE / 2];       // (src,w,src,w) pairs grouped by dst
__device__ int   g_is64;

__device__ __forceinline__ const __half* hsel(int s) {
    switch (s) {
        case 0:  return g_xh;
        case 1:  return g_h0;
        case 2:  return g_h1;
        default: return g_h2;
    }
}
__device__ __forceinline__ __half* hdst(int s) {
    switch (s) {
        case 1:  return g_h0;
        case 2:  return g_h1;
        default: return g_h2;
    }
}
__device__ __forceinline__ const __half* wsel(int s) {
    switch (s) {
        case 1:  return g_w1;
        case 2:  return g_w2;
        default: return g_w3;
    }
}

__device__ __forceinline__ int clampN(int v) {
    return (v < 0) ? 0 : ((v >= NN) ? NN - 1 : v);
}
__device__ __forceinline__ int edge_at(const int* __restrict__ p32, int row, int e, int is64) {
    long long idx = (long long)row * EE + e;
    return is64 ? p32[2 * idx] : p32[idx];
}

__device__ __forceinline__ unsigned smem_u32(const void* p) {
    return (unsigned)__cvta_generic_to_shared(p);
}
__device__ __forceinline__ void ldm_x4(unsigned& r0, unsigned& r1, unsigned& r2, unsigned& r3, unsigned a) {
    asm volatile("ldmatrix.sync.aligned.m8n8.x4.shared.b16 {%0,%1,%2,%3}, [%4];"
                 : "=r"(r0), "=r"(r1), "=r"(r2), "=r"(r3) : "r"(a));
}
__device__ __forceinline__ void ldm_x4_t(unsigned& r0, unsigned& r1, unsigned& r2, unsigned& r3, unsigned a) {
    asm volatile("ldmatrix.sync.aligned.m8n8.x4.trans.shared.b16 {%0,%1,%2,%3}, [%4];"
                 : "=r"(r0), "=r"(r1), "=r"(r2), "=r"(r3) : "r"(a));
}
__device__ __forceinline__ void mma16816(float* c, unsigned a0, unsigned a1, unsigned a2, unsigned a3,
                                         unsigned b0, unsigned b1) {
    asm volatile("mma.sync.aligned.m16n8k16.row.col.f32.f16.f16.f32 "
                 "{%0,%1,%2,%3}, {%4,%5,%6,%7}, {%8,%9}, {%0,%1,%2,%3};"
                 : "+f"(c[0]), "+f"(c[1]), "+f"(c[2]), "+f"(c[3])
                 : "r"(a0), "r"(a1), "r"(a2), "r"(a3), "r"(b0), "r"(b1));
}

// ---------------- fused prep (fp32->fp16) + zero counters/flags + dtype detect ----------------
__global__ void prep_zero_kernel(const float* __restrict__ x,
                                 const float* __restrict__ W1,
                                 const float* __restrict__ W2,
                                 const float* __restrict__ W3,
                                 const float* __restrict__ Wl,
                                 const int* __restrict__ p32) {
    int bid = blockIdx.x;
    if (bid < PREPB) {
        int idx = bid * 256 + threadIdx.x;
        if (idx < XV4) {
            float4 v = ((const float4*)x)[idx];
            __half2* xo = (__half2*)g_xh;
            xo[idx * 2 + 0] = __floats2half2_rn(v.x, v.y);
            xo[idx * 2 + 1] = __floats2half2_rn(v.z, v.w);
            return;
        }
        int j = idx - XV4;
        if (j < IND * 64) { g_w1[j] = __float2half_rn(W1[j]); return; }
        j -= IND * 64;
        if (j < HID * 64) { g_w2[j] = __float2half_rn(W2[j]); return; }
        j -= HID * 64;
        if (j < HID * 64) { g_w3[j] = __float2half_rn(W3[j]); return; }
        j -= HID * 64;
        if (j < 192 * 64) {
            int k = j >> 6, c = j & 63;
            g_wl[j] = (c < OUTD) ? __float2half_rn(Wl[k * OUTD + c]) : __float2half_rn(0.f);
        }
        return;
    }
    // zero section
    int zb = bid - PREPB;
    int i = zb * 256 + threadIdx.x;
    if (i < NN) g_cnt[i] = 0;
    if (i < NBLK) g_flag[i] = 0;
    if (zb == 0 && threadIdx.x < 32) {
        int lane = threadIdx.x;
        int any = p32[2 * lane + 1] | p32[2 * (lane + 32) + 1];
        unsigned nz = __ballot_sync(0xFFFFFFFFu, any != 0);
        if (lane == 0) g_is64 = (nz == 0) ? 1 : 0;
    }
}

// ---------------- histogram ----------------
__global__ void hist_kernel(const int* __restrict__ ei32) {
    int e = blockIdx.x * blockDim.x + threadIdx.x;
    if (e < EE) {
        int d = clampN(edge_at(ei32, 1, e, g_is64));
        atomicAdd(&g_cnt[d], 1);
    }
}

// ---------------- single-pass scan (publish aggregate + all-pred lookback) ----------------
// helper: exclusive scan over 256 threads; wsum[7] ends holding the block total.
__device__ __forceinline__ int block_excl_scan_256(int v, int tid, int* wsum) {
    int lane = tid & 31, w = tid >> 5;
    int x = v;
#pragma unroll
    for (int o = 1; o < 32; o <<= 1) {
        int y = __shfl_up_sync(0xFFFFFFFFu, x, o);
        if (lane >= o) x += y;
    }
    if (lane == 31) wsum[w] = x;
    __syncthreads();
    if (w == 0) {
        int s = (lane < 8) ? wsum[lane] : 0;
#pragma unroll
        for (int o = 1; o < 8; o <<= 1) {
            int y = __shfl_up_sync(0xFFFFFFFFu, s, o);
            if (lane >= o) s += y;
        }
        if (lane < 8) wsum[lane] = s;
    }
    __syncthreads();
    int incl = x + ((w > 0) ? wsum[w - 1] : 0);
    return incl - v;
}

__global__ void __launch_bounds__(256) scan_kernel() {
    __shared__ int wsum[8];
    __shared__ int s_off;
    int tid = threadIdx.x, b = blockIdx.x;

    int i = b * 256 + tid;
    int c = (i < NN) ? g_cnt[i] : 0;
    int excl = block_excl_scan_256(c, tid, wsum);
    int total = wsum[7];

    if (tid == 0) {
        g_agg[b] = total;
        __threadfence();
        *(volatile int*)&g_flag[b] = 1;
    }

    // lookback: warp 0 sums aggregates of all predecessor blocks
    if (tid < 32) {
        int sum = 0;
        for (int p = tid; p < b; p += 32) {
            while (*(volatile int*)&g_flag[p] == 0) { }
            sum += *(volatile int*)&g_agg[p];
        }
#pragma unroll
        for (int o = 16; o > 0; o >>= 1) sum += __shfl_down_sync(0xFFFFFFFFu, sum, o);
        if (tid == 0) s_off = sum;
    }
    __syncthreads();
    int off = s_off;

    if (i < NN) {
        g_rowptr[i] = off + excl;
        g_cnt[i] = 0;   // reset cursors for fill
    }
    if (b == NBLK - 1 && tid == 0) g_rowptr[NN] = off + total;
}

__global__ void fill_kernel(const int* __restrict__ ei32,
                            const float* __restrict__ ew) {
    int e = blockIdx.x * blockDim.x + threadIdx.x;
    if (e < EE) {
        int is64 = g_is64;
        int d = clampN(edge_at(ei32, 1, e, is64));
        int s = clampN(edge_at(ei32, 0, e, is64));
        int pos = g_rowptr[d] + atomicAdd(&g_cnt[d], 1);
        ((int2*)g_edge4)[pos] = make_int2(s, __float_as_int(ew[e]));
    }
}

// ---------------- tensor-core GEMM: g_hlin[N,64] = X[N,K] @ W[K,64] (fp16) ----------------
template <int K>
__global__ void __launch_bounds__(128) gemm_mma_kernel(int src_sel, int w_sel) {
    constexpr int XS = K + 8;
    __shared__ __half Xs[64 * XS];
    __shared__ __half Ws[K * 72];

    int tid = threadIdx.x, warp = tid >> 5, lane = tid & 31;
    int row0 = blockIdx.x * 64;

    const __half* X = hsel(src_sel);
    const __half* Wp = wsel(w_sel);

    constexpr int NV = K / 8;
    for (int i = tid; i < 64 * NV; i += 128) {
        int r = i / NV, c = i % NV;
        int gr = row0 + r; if (gr >= NN) gr = NN - 1;
        *(uint4*)&Xs[r * XS + c * 8] = *(const uint4*)&X[(size_t)gr * K + c * 8];
    }
    for (int i = tid; i < K * 8; i += 128) {
        int r = i >> 3, c = i & 7;
        *(uint4*)&Ws[r * 72 + c * 8] = *(const uint4*)&Wp[r * 64 + c * 8];
    }
    __syncthreads();

    int wr = warp * 16;
    float acc[8][4];
#pragma unroll
    for (int g = 0; g < 8; g++) { acc[g][0] = acc[g][1] = acc[g][2] = acc[g][3] = 0.f; }

    unsigned xb = smem_u32(Xs), wb = smem_u32(Ws);
    int arow = wr + ((lane >> 3) & 1) * 8 + (lane & 7);
    int acol8 = (lane >> 4) * 8;
    int brow8 = ((lane >> 3) & 1) * 8 + (lane & 7);

#pragma unroll
    for (int kk = 0; kk < K / 16; kk++) {
        unsigned a0, a1, a2, a3;
        ldm_x4(a0, a1, a2, a3, xb + (arow * XS + kk * 16 + acol8) * 2);
#pragma unroll
        for (int jn = 0; jn < 4; jn++) {
            unsigned b0, b1, b2, b3;
            ldm_x4_t(b0, b1, b2, b3, wb + ((kk * 16 + brow8) * 72 + jn * 16 + acol8) * 2);
            mma16816(acc[jn * 2 + 0], a0, a1, a2, a3, b0, b1);
            mma16816(acc[jn * 2 + 1], a0, a1, a2, a3, b2, b3);
        }
    }

    __half2* hl = (__half2*)g_hlin;
    int g = lane >> 2, q = lane & 3;
#pragma unroll
    for (int gn = 0; gn < 8; gn++) {
        int r0 = row0 + wr + g, r1 = r0 + 8;
        int cidx = gn * 4 + q;
        if (r0 < NN) hl[(size_t)r0 * 32 + cidx] = __floats2half2_rn(acc[gn][0], acc[gn][1]);
        if (r1 < NN) hl[(size_t)r1 * 32 + cidx] = __floats2half2_rn(acc[gn][2], acc[gn][3]);
    }
}

// ---------------- aggregation: warp per node, int4 paired edge loads ----------------
__global__ void __launch_bounds__(256) agg_kernel(int dst_sel,
                                                  const float* __restrict__ bias) {
    int gw   = (blockIdx.x * 256 + threadIdx.x) >> 5;
    int lane = threadIdx.x & 31;
    if (gw >= NN) return;

    const __half2* hl = (const __half2*)g_hlin;
    const int2*    ed = (const int2*)g_edge4;
    __half2*       hout = (__half2*)hdst(dst_sel);

    int beg = g_rowptr[gw], end = g_rowptr[gw + 1];
    float a0 = 0.f, a1 = 0.f, c0 = 0.f, c1 = 0.f;

    int e = beg;
    if ((e & 1) && e < end) {           // parity peel for int4 alignment
        int2 E = ed[e];
        float2 h = __half22float2(hl[(size_t)E.x * 32 + lane]);
        float w = __int_as_float(E.y);
        a0 = fmaf(w, h.x, a0); a1 = fmaf(w, h.y, a1);
        e++;
    }
    for (; e + 4 <= end; e += 4) {
        int4 Ea = g_edge4[e >> 1];
        int4 Eb = g_edge4[(e >> 1) + 1];
        float2 h0 = __half22float2(hl[(size_t)Ea.x * 32 + lane]);
        float2 h1 = __half22float2(hl[(size_t)Ea.z * 32 + lane]);
        float2 h2 = __half22float2(hl[(size_t)Eb.x * 32 + lane]);
        float2 h3 = __half22float2(hl[(size_t)Eb.z * 32 + lane]);
        float w0 = __int_as_float(Ea.y), w1 = __int_as_float(Ea.w);
        float w2 = __int_as_float(Eb.y), w3 = __int_as_float(Eb.w);
        a0 = fmaf(w0, h0.x, a0); a1 = fmaf(w0, h0.y, a1);
        c0 = fmaf(w1, h1.x, c0); c1 = fmaf(w1, h1.y, c1);
        a0 = fmaf(w2, h2.x, a0); a1 = fmaf(w2, h2.y, a1);
        c0 = fmaf(w3, h3.x, c0); c1 = fmaf(w3, h3.y, c1);
    }
    if (e + 2 <= end) {
        int4 Ea = g_edge4[e >> 1];
        float2 h0 = __half22float2(hl[(size_t)Ea.x * 32 + lane]);
        float2 h1 = __half22float2(hl[(size_t)Ea.z * 32 + lane]);
        float w0 = __int_as_float(Ea.y), w1 = __int_as_float(Ea.w);
        a0 = fmaf(w0, h0.x, a0); a1 = fmaf(w0, h0.y, a1);
        c0 = fmaf(w1, h1.x, c0); c1 = fmaf(w1, h1.y, c1);
        e += 2;
    }
    if (e < end) {
        int2 E = ed[e];
        float2 h = __half22float2(hl[(size_t)E.x * 32 + lane]);
        float w = __int_as_float(E.y);
        a0 = fmaf(w, h.x, a0); a1 = fmaf(w, h.y, a1);
    }
    a0 += c0; a1 += c1;

    float b0 = bias[lane * 2], b1 = bias[lane * 2 + 1];
    hout[(size_t)gw * 32 + lane] =
        __floats2half2_rn(fmaxf(a0 + b0, 0.f), fmaxf(a1 + b1, 0.f));
}

// ---------------- final: out[N,40] = [h0|h1|h2] @ Wlin + blin (tensor cores) ----------------
__global__ void __launch_bounds__(128) final_mma_kernel(const float* __restrict__ blin,
                                                        float* __restrict__ out) {
    constexpr int XS = 72;
    __shared__ __half Xs[64 * XS];
    __shared__ __half Ws[192 * 72];

    int tid = threadIdx.x, warp = tid >> 5, lane = tid & 31;
    int row0 = blockIdx.x * 64;

    for (int i = tid; i < 192 * 8; i += 128) {
        int r = i >> 3, c = i & 7;
        *(uint4*)&Ws[r * 72 + c * 8] = *(const uint4*)&g_wl[r * 64 + c * 8];
    }

    int wr = warp * 16;
    float acc[8][4];
#pragma unroll
    for (int g = 0; g < 8; g++) { acc[g][0] = acc[g][1] = acc[g][2] = acc[g][3] = 0.f; }

    unsigned xb = smem_u32(Xs), wb = smem_u32(Ws);
    int arow = wr + ((lane >> 3) & 1) * 8 + (lane & 7);
    int acol8 = (lane >> 4) * 8;
    int brow8 = ((lane >> 3) & 1) * 8 + (lane & 7);

#pragma unroll 1
    for (int l = 0; l < 3; l++) {
        const __half* H = hsel(1 + l);
        __syncthreads();
        for (int i = tid; i < 64 * 8; i += 128) {
            int r = i >> 3, c = i & 7;
            int gr = row0 + r; if (gr >= NN) gr = NN - 1;
            *(uint4*)&Xs[r * XS + c * 8] = *(const uint4*)&H[(size_t)gr * 64 + c * 8];
        }
        __syncthreads();

#pragma unroll
        for (int kk = 0; kk < 4; kk++) {
            unsigned a0, a1, a2, a3;
            ldm_x4(a0, a1, a2, a3, xb + (arow * XS + kk * 16 + acol8) * 2);
#pragma unroll
            for (int jn = 0; jn < 4; jn++) {
                unsigned b0, b1, b2, b3;
                ldm_x4_t(b0, b1, b2, b3,
                         wb + ((l * 64 + kk * 16 + brow8) * 72 + jn * 16 + acol8) * 2);
                mma16816(acc[jn * 2 + 0], a0, a1, a2, a3, b0, b1);
                mma16816(acc[jn * 2 + 1], a0, a1, a2, a3, b2, b3);
            }
        }
    }

    int g = lane >> 2, q = lane & 3;
#pragma unroll
    for (int gn = 0; gn < 5; gn++) {
        int col = gn * 8 + q * 2;
        if (col >= OUTD) continue;
        float b0 = blin[col], b1 = blin[col + 1];
        int r0 = row0 + wr + g, r1 = r0 + 8;
        if (r0 < NN) {
            float2 o; o.x = acc[gn][0] + b0; o.y = acc[gn][1] + b1;
            *(float2*)&out[(size_t)r0 * OUTD + col] = o;
        }
        if (r1 < NN) {
            float2 o; o.x = acc[gn][2] + b0; o.y = acc[gn][3] + b1;
            *(float2*)&out[(size_t)r1 * OUTD + col] = o;
        }
    }
}

// ---------------- launch ----------------
extern "C" void kernel_launch(void* const* d_in, const int* in_sizes, int n_in,
                              void* d_out, int out_size) {
    const float* x    = (const float*)d_in[0];
    const int*   ei32 = (const int*)d_in[1];
    const float* ew   = (const float*)d_in[2];
    const float* W1 = (const float*)d_in[3];
    const float* b1 = (const float*)d_in[4];
    const float* W2 = (const float*)d_in[5];
    const float* b2 = (const float*)d_in[6];
    const float* W3 = (const float*)d_in[7];
    const float* b3 = (const float*)d_in[8];
    const float* Wl = (const float*)d_in[9];
    const float* bl = (const float*)d_in[10];
    float* out = (float*)d_out;

    const int AB = (NN * 32 + 255) / 256;     // 6250

    static cudaStream_t s2 = nullptr;
    static cudaEvent_t evFork = nullptr, evJoin = nullptr;
    if (!s2) {
        cudaStreamCreateWithFlags(&s2, cudaStreamNonBlocking);
        cudaEventCreateWithFlags(&evFork, cudaEventDisableTiming);
        cudaEventCreateWithFlags(&evJoin, cudaEventDisableTiming);
    }

    // stage 0: conversions + counter zeroing (main stream)
    prep_zero_kernel<<<PREPB + NBLK, 256>>>(x, W1, W2, W3, Wl, ei32);

    // fork: CSC chain on side stream, gemm1 concurrently on main stream
    cudaEventRecord(evFork, 0);
    cudaStreamWaitEvent(s2, evFork, 0);
    hist_kernel<<<HB, 256, 0, s2>>>(ei32);
    scan_kernel<<<NBLK, 256, 0, s2>>>();
    fill_kernel<<<HB, 256, 0, s2>>>(ei32, ew);
    cudaEventRecord(evJoin, s2);

    gemm_mma_kernel<IND><<<GB, 128>>>(0, 1);   // main stream, parallel with CSC

    cudaStreamWaitEvent(0, evJoin, 0);         // join

    agg_kernel<<<AB, 256>>>(1, b1);
    gemm_mma_kernel<HID><<<GB, 128>>>(1, 2);
    agg_kernel<<<AB, 256>>>(2, b2);
    gemm_mma_kernel<HID><<<GB, 128>>>(2, 3);
    agg_kernel<<<AB, 256>>>(3, b3);
    final_mma_kernel<<<GB, 128>>>(bl, out);
}